// round 13
// baseline (speedup 1.0000x reference)
#include <cuda_runtime.h>
#include <cuda_fp16.h>
#include <cstdint>

#define KDIM 1024
#define IDIM 64
#define ODIM 1024
#define THREADS 256
#define NT 64                   // CTA N tile
#define KC 32                   // k per chunk
#define NCHUNK (KDIM / KC)      // 32

// 64B-row tiles, SW64 XOR swizzle (conflict-free for ldmatrix phases)
#define SWZ64(o) ((uint32_t)(o) ^ ((((uint32_t)(o)) >> 3) & 0x30))
#define TILE_A 8192             // A fp16 tile: 128 x 32 fp16
#define TILE_B16 4096           // B fp16 tile: 64 x 32 fp16

#define OFF_A 0                      // 3 buffers: +0, +8192, +16384
#define OFF_B16 (3 * TILE_A)         // 24576: 2 buffers
#define SMEM_DYN (OFF_B16 + 2 * TILE_B16)   // 32768 -> 3 CTAs/SM

// Pre-converted x: tile (i, ch) = 8 KB at ((i*32+ch)*8192); swizzled
// [b(128) x 32 fp16] rows of 64B.
__device__ unsigned char g_xh[64 * 32 * 8192];

static __device__ __forceinline__ uint32_t smem_u32(const void* p) {
    uint32_t a;
    asm("{ .reg .u64 t; cvta.to.shared.u64 t, %1; cvt.u32.u64 %0, t; }"
        : "=r"(a) : "l"(p));
    return a;
}

static __device__ __forceinline__ void ldm_x4(uint32_t* r, uint32_t addr) {
    asm volatile(
        "ldmatrix.sync.aligned.m8n8.x4.shared.b16 {%0,%1,%2,%3}, [%4];"
        : "=r"(r[0]), "=r"(r[1]), "=r"(r[2]), "=r"(r[3]) : "r"(addr));
}

static __device__ __forceinline__ void mma_f16(float* d, const uint32_t* a,
                                               const uint32_t* b) {
    asm volatile(
        "mma.sync.aligned.m16n8k16.row.col.f32.f16.f16.f32 "
        "{%0,%1,%2,%3}, {%4,%5,%6,%7}, {%8,%9}, {%0,%1,%2,%3};"
        : "+f"(d[0]), "+f"(d[1]), "+f"(d[2]), "+f"(d[3])
        : "r"(a[0]), "r"(a[1]), "r"(a[2]), "r"(a[3]), "r"(b[0]), "r"(b[1]));
}

static __device__ __forceinline__ void cp16(uint32_t saddr, const void* gaddr) {
    asm volatile("cp.async.cg.shared.global [%0], [%1], 16;"
                 :: "r"(saddr), "l"(gaddr));
}

// Pack float4 -> 2 fp16x2 with single-instruction converts.
static __device__ __forceinline__ uint2 pack_hi4(const float4 v) {
    uint2 r;
    asm("cvt.rn.f16x2.f32 %0, %1, %2;" : "=r"(r.x) : "f"(v.y), "f"(v.x));
    asm("cvt.rn.f16x2.f32 %0, %1, %2;" : "=r"(r.y) : "f"(v.w), "f"(v.z));
    return r;
}

// ───────────── pre-pass: x fp32 -> swizzled fp16 tiles ─────────────
__global__ void __launch_bounds__(THREADS)
cvt_x_kernel(const float* __restrict__ x) {
    const int i = blockIdx.x;    // 0..63
    const int ch = blockIdx.y;   // 0..31
    unsigned char* tile = g_xh + ((size_t)i * NCHUNK + ch) * TILE_A;
    const float* src = x + (size_t)i * KDIM + ch * KC;
#pragma unroll
    for (int it = 0; it < 4; ++it) {
        int f = threadIdx.x + it * THREADS;   // float4 idx 0..1023
        int b = f >> 3;
        int c4 = f & 7;
        const float4 v = *reinterpret_cast<const float4*>(
            src + (size_t)b * (IDIM * KDIM) + c4 * 4);
        *reinterpret_cast<uint2*>(tile + SWZ64(b * 64 + c4 * 8)) = pack_hi4(v);
    }
}

// ───────────── main GEMM ─────────────

// cp.async one A fp16 tile (8 KB, already swizzled) into smem.
static __device__ __forceinline__ void stage_a(uint32_t dst,
                                               const unsigned char* tile) {
#pragma unroll
    for (int it = 0; it < 2; ++it) {
        int g = threadIdx.x + it * THREADS;   // 16B granule, 0..511
        cp16(dst + (uint32_t)(g * 16), tile + (size_t)g * 16);
    }
}

// LDG one B fp32 chunk [64 x 32] into registers (2 float4 per thread).
#define LDG_B(bregs, gb)                                                       \
    do {                                                                       \
        _Pragma("unroll") for (int it_ = 0; it_ < 2; ++it_) {                  \
            int f_ = threadIdx.x + it_ * THREADS;                              \
            int row_ = f_ >> 3, c4_ = f_ & 7;                                  \
            (bregs)[it_] = *reinterpret_cast<const float4*>(                   \
                (gb) + (size_t)row_ * 65536 + c4_ * 4);                        \
        }                                                                      \
    } while (0)

// Convert register-held B fp32 -> swizzled fp16 tile in smem.
#define CVT_B(bregs, sm, dst_off)                                              \
    do {                                                                       \
        _Pragma("unroll") for (int it_ = 0; it_ < 2; ++it_) {                  \
            int f_ = threadIdx.x + it_ * THREADS;                              \
            int row_ = f_ >> 3, c4_ = f_ & 7;                                  \
            *reinterpret_cast<uint2*>((sm) + (dst_off) +                       \
                                      SWZ64(row_ * 64 + c4_ * 8)) =            \
                pack_hi4((bregs)[it_]);                                        \
        }                                                                      \
    } while (0)

__global__ void __launch_bounds__(THREADS, 3)
fl_kernel(const float* __restrict__ w, const float* __restrict__ bias,
          float* __restrict__ out) {
    extern __shared__ char sm[];
    const uint32_t sbase = smem_u32(sm);
    const int tid = threadIdx.x;
    const int wid = tid >> 5;
    const int lid = tid & 31;
    const int warp_m = wid >> 1;   // 0..3 : 32 M rows each
    const int warp_n = wid & 1;    // 0..1 : 32 N cols each
    const int otile = blockIdx.x;  // 0..15
    const int i_idx = blockIdx.y;  // 0..63

    const unsigned char* xtiles = g_xh + (size_t)i_idx * NCHUNK * TILE_A;
    const float* wa = w + ((size_t)otile * NT) * (IDIM * KDIM) + (size_t)i_idx * KDIM;

    float acc[2][4][4];
#pragma unroll
    for (int a = 0; a < 2; ++a)
#pragma unroll
        for (int b = 0; b < 4; ++b)
#pragma unroll
            for (int c = 0; c < 4; ++c) acc[a][b][c] = 0.0f;

    const uint32_t a_row = (uint32_t)(warp_m * 32 + (lid & 15));
    const uint32_t a_cb = (uint32_t)((lid >> 4) * 16);
    const uint32_t b_row = (uint32_t)(warp_n * 32 + ((lid >> 4) << 3) + (lid & 7));
    const uint32_t b_cb = (uint32_t)(((lid >> 3) & 1) * 16);

    // Prologue: A chunks 0,1 via cp.async (groups 0,1); B chunk 0 converted,
    // B chunk 1 resident in regs.
    float4 bregs[2];
    stage_a(sbase + OFF_A + 0 * TILE_A, xtiles);
    asm volatile("cp.async.commit_group;" ::: "memory");
    stage_a(sbase + OFF_A + 1 * TILE_A, xtiles + TILE_A);
    asm volatile("cp.async.commit_group;" ::: "memory");
    LDG_B(bregs, wa);
    CVT_B(bregs, sm, OFF_B16 + 0 * TILE_B16);
    LDG_B(bregs, wa + KC);
    asm volatile("cp.async.wait_group 1;" ::: "memory");
    __syncthreads();

    int a_slot = 0;   // A buffer index of current chunk (mod 3)
    for (int ch = 0; ch < NCHUNK; ++ch) {
        const int a_next2 = (a_slot + 2 >= 3) ? (a_slot - 1) : (a_slot + 2);
        const bool pf = (ch + 2 < NCHUNK);

        // Prefetch A(ch+2) (group ch+2).
        if (pf) {
            stage_a(sbase + OFF_A + (uint32_t)(a_next2 * TILE_A),
                    xtiles + (size_t)(ch + 2) * TILE_A);
            asm volatile("cp.async.commit_group;" ::: "memory");
        }

        // MMA on A[a_slot], B16[ch&1]: 2 K=16 steps
        const uint32_t abuf = sbase + OFF_A + (uint32_t)(a_slot * TILE_A);
        const uint32_t bbuf = sbase + OFF_B16 + (uint32_t)((ch & 1) * TILE_B16);
#pragma unroll
        for (int ks = 0; ks < 2; ++ks) {
            uint32_t ah[2][4], bh[2][4];
#pragma unroll
            for (int mt = 0; mt < 2; ++mt)
                ldm_x4(ah[mt], abuf +
                       SWZ64((a_row + mt * 16) * 64 + ks * 32 + a_cb));
#pragma unroll
            for (int bt = 0; bt < 2; ++bt)
                ldm_x4(bh[bt], bbuf +
                       SWZ64((b_row + bt * 16) * 64 + ks * 32 + b_cb));
#pragma unroll
            for (int mt = 0; mt < 2; ++mt)
#pragma unroll
                for (int nt = 0; nt < 4; ++nt)
                    mma_f16(acc[mt][nt], ah[mt], &bh[nt >> 1][(nt & 1) * 2]);
        }

        // Convert B(ch+1) (resident in regs), then load B(ch+2) into regs —
        // a full chunk of latency cover before its convert next iteration.
        if (ch + 1 < NCHUNK) {
            CVT_B(bregs, sm, OFF_B16 + (uint32_t)(((ch + 1) & 1) * TILE_B16));
            if (ch + 2 < NCHUNK) {
                LDG_B(bregs, wa + (ch + 2) * KC);
            }
        }

        // Ensure A(ch+1) landed (group ch+2 may stay in flight).
        if (pf) {
            asm volatile("cp.async.wait_group 1;" ::: "memory");
        } else {
            asm volatile("cp.async.wait_group 0;" ::: "memory");
        }
        __syncthreads();

        a_slot = (a_slot + 1 >= 3) ? 0 : (a_slot + 1);
    }

    // Epilogue: add bias, store. out[b][o][i] = b*65536 + o*64 + i
    const float* bp = bias + (size_t)(otile * NT) * IDIM + i_idx;
    float bv[4][2];
#pragma unroll
    for (int nt = 0; nt < 4; ++nt) {
        int n_l = warp_n * 32 + nt * 8 + 2 * (lid & 3);
        bv[nt][0] = bp[(size_t)n_l * IDIM];
        bv[nt][1] = bp[(size_t)(n_l + 1) * IDIM];
    }
#pragma unroll
    for (int mt = 0; mt < 2; ++mt) {
        int m0 = warp_m * 32 + mt * 16 + (lid >> 2);
#pragma unroll
        for (int nt = 0; nt < 4; ++nt) {
            int n_l = warp_n * 32 + nt * 8 + 2 * (lid & 3);
            float* o0 = out + (size_t)m0 * (ODIM * IDIM) +
                        (size_t)(otile * NT + n_l) * IDIM + i_idx;
            o0[0] = acc[mt][nt][0] + bv[nt][0];
            o0[IDIM] = acc[mt][nt][1] + bv[nt][1];
            float* o8 = o0 + (size_t)8 * (ODIM * IDIM);
            o8[0] = acc[mt][nt][2] + bv[nt][0];
            o8[IDIM] = acc[mt][nt][3] + bv[nt][1];
        }
    }
}

extern "C" void kernel_launch(void* const* d_in, const int* in_sizes, int n_in,
                              void* d_out, int out_size) {
    (void)in_sizes; (void)n_in; (void)out_size;
    const float* x = (const float*)d_in[0];
    const float* w = (const float*)d_in[1];
    const float* bias = (const float*)d_in[2];
    float* out = (float*)d_out;

    cvt_x_kernel<<<dim3(IDIM, NCHUNK), THREADS>>>(x);

    cudaFuncSetAttribute(fl_kernel, cudaFuncAttributeMaxDynamicSharedMemorySize,
                         SMEM_DYN);
    fl_kernel<<<dim3(ODIM / NT, IDIM), THREADS, SMEM_DYN>>>(w, bias, out);
}

// round 14
// speedup vs baseline: 1.0838x; 1.0838x over previous
#include <cuda_runtime.h>
#include <cuda_fp16.h>
#include <cstdint>

#define KDIM 1024
#define IDIM 64
#define ODIM 1024
#define THREADS 256
#define KC 32                   // k per chunk
#define NCHUNK (KDIM / KC)      // 32

// 64B-row tiles, SW64 XOR swizzle (conflict-free for ldmatrix phases)
#define SWZ64(o) ((uint32_t)(o) ^ ((((uint32_t)(o)) >> 3) & 0x30))
#define TILE_A 8192             // A fp16 tile: 128 x 32 fp16
#define TILE_B16 8192           // B fp16 tile: 128 x 32 fp16

#define OFF_A 0                      // 3 buffers: +0, +8192, +16384
#define OFF_B16 (3 * TILE_A)         // 24576: 2 buffers
#define SMEM_DYN (OFF_B16 + 2 * TILE_B16)   // 40960

// Pre-converted x: tile (i, ch) = 8 KB at ((i*32+ch)*8192); swizzled
// [b(128) x 32 fp16] rows of 64B.
__device__ unsigned char g_xh[64 * 32 * 8192];

static __device__ __forceinline__ uint32_t smem_u32(const void* p) {
    uint32_t a;
    asm("{ .reg .u64 t; cvta.to.shared.u64 t, %1; cvt.u32.u64 %0, t; }"
        : "=r"(a) : "l"(p));
    return a;
}

static __device__ __forceinline__ void ldm_x4(uint32_t* r, uint32_t addr) {
    asm volatile(
        "ldmatrix.sync.aligned.m8n8.x4.shared.b16 {%0,%1,%2,%3}, [%4];"
        : "=r"(r[0]), "=r"(r[1]), "=r"(r[2]), "=r"(r[3]) : "r"(addr));
}

static __device__ __forceinline__ void mma_f16(float* d, const uint32_t* a,
                                               const uint32_t* b) {
    asm volatile(
        "mma.sync.aligned.m16n8k16.row.col.f32.f16.f16.f32 "
        "{%0,%1,%2,%3}, {%4,%5,%6,%7}, {%8,%9}, {%0,%1,%2,%3};"
        : "+f"(d[0]), "+f"(d[1]), "+f"(d[2]), "+f"(d[3])
        : "r"(a[0]), "r"(a[1]), "r"(a[2]), "r"(a[3]), "r"(b[0]), "r"(b[1]));
}

static __device__ __forceinline__ void cp16(uint32_t saddr, const void* gaddr) {
    asm volatile("cp.async.cg.shared.global [%0], [%1], 16;"
                 :: "r"(saddr), "l"(gaddr));
}

// Pack float4 -> 2 fp16x2 with single-instruction converts.
static __device__ __forceinline__ uint2 pack_hi4(const float4 v) {
    uint2 r;
    asm("cvt.rn.f16x2.f32 %0, %1, %2;" : "=r"(r.x) : "f"(v.y), "f"(v.x));
    asm("cvt.rn.f16x2.f32 %0, %1, %2;" : "=r"(r.y) : "f"(v.w), "f"(v.z));
    return r;
}

// ───────────── pre-pass: x fp32 -> swizzled fp16 tiles (coalesced) ─────────
// CTA = (i, b-block of 16). Reads are 4KB-contiguous runs per batch row.
__global__ void __launch_bounds__(THREADS)
cvt_x_kernel(const float* __restrict__ x) {
    const int i = blockIdx.x;     // 0..63
    const int bb = blockIdx.y;    // 0..7 (16 batch rows each)
    unsigned char* tiles = g_xh + (size_t)i * NCHUNK * TILE_A;
#pragma unroll
    for (int it = 0; it < 16; ++it) {
        int f = threadIdx.x + it * THREADS;   // 0..4095 float4 over [16b x 256c4]
        int b_loc = f >> 8;                   // 0..15
        int c4 = f & 255;                     // float4 index within the k row
        int b = bb * 16 + b_loc;
        const float4 v = *reinterpret_cast<const float4*>(
            x + (size_t)b * (IDIM * KDIM) + (size_t)i * KDIM + c4 * 4);
        int ch = c4 >> 3;                     // 32 k per chunk = 8 float4
        uint32_t boff = (uint32_t)(b * 64 + (c4 & 7) * 8);
        *reinterpret_cast<uint2*>(tiles + (size_t)ch * TILE_A + SWZ64(boff)) =
            pack_hi4(v);
    }
}

// ───────────── main GEMM ─────────────

// cp.async one A fp16 tile (8 KB, already swizzled) into smem.
static __device__ __forceinline__ void stage_a(uint32_t dst,
                                               const unsigned char* tile) {
#pragma unroll
    for (int it = 0; it < 2; ++it) {
        int g = threadIdx.x + it * THREADS;   // 16B granule, 0..511
        cp16(dst + (uint32_t)(g * 16), tile + (size_t)g * 16);
    }
}

// LDG one B fp32 chunk [128 x 32] into registers (4 float4 per thread).
#define LDG_B(bregs, gb)                                                       \
    do {                                                                       \
        _Pragma("unroll") for (int it_ = 0; it_ < 4; ++it_) {                  \
            int f_ = threadIdx.x + it_ * THREADS;                              \
            int row_ = f_ >> 3, c4_ = f_ & 7;                                  \
            (bregs)[it_] = *reinterpret_cast<const float4*>(                   \
                (gb) + (size_t)row_ * 65536 + c4_ * 4);                        \
        }                                                                      \
    } while (0)

// Convert register-held B fp32 -> swizzled fp16 tile in smem.
#define CVT_B(bregs, sm, dst_off)                                              \
    do {                                                                       \
        _Pragma("unroll") for (int it_ = 0; it_ < 4; ++it_) {                  \
            int f_ = threadIdx.x + it_ * THREADS;                              \
            int row_ = f_ >> 3, c4_ = f_ & 7;                                  \
            *reinterpret_cast<uint2*>((sm) + (dst_off) +                       \
                                      SWZ64(row_ * 64 + c4_ * 8)) =            \
                pack_hi4((bregs)[it_]);                                        \
        }                                                                      \
    } while (0)

__global__ void __launch_bounds__(THREADS, 2)
fl_kernel(const float* __restrict__ w, const float* __restrict__ bias,
          float* __restrict__ out) {
    extern __shared__ char sm[];
    const uint32_t sbase = smem_u32(sm);
    const int tid = threadIdx.x;
    const int wid = tid >> 5;
    const int lid = tid & 31;
    const int warp_m = wid >> 2;   // 0..1 : 64 M rows each
    const int warp_n = wid & 3;    // 0..3 : 32 N cols each
    const int otile = blockIdx.x;  // 0..7
    const int i_idx = blockIdx.y;  // 0..63

    // De-phase co-resident CTAs: half start their K-walk at chunk 16.
    const int start = ((blockIdx.x ^ blockIdx.y) & 1) * (NCHUNK / 2);

    const unsigned char* xtiles = g_xh + (size_t)i_idx * NCHUNK * TILE_A;
    const float* wa = w + ((size_t)otile * 128) * (IDIM * KDIM) + (size_t)i_idx * KDIM;

    float acc[4][4][4];
#pragma unroll
    for (int a = 0; a < 4; ++a)
#pragma unroll
        for (int b = 0; b < 4; ++b)
#pragma unroll
            for (int c = 0; c < 4; ++c) acc[a][b][c] = 0.0f;

    const uint32_t a_row = (uint32_t)(warp_m * 64 + (lid & 15));
    const uint32_t a_cb = (uint32_t)((lid >> 4) * 16);
    const uint32_t b_row = (uint32_t)(warp_n * 32 + ((lid >> 4) << 3) + (lid & 7));
    const uint32_t b_cb = (uint32_t)(((lid >> 3) & 1) * 16);

    // Prologue: A chunks c0,c1 via cp.async (groups 0,1); B chunk c0 converted,
    // B chunk c1 resident in regs.
    float4 bregs[4];
    {
        const int c0 = start;
        const int c1 = (start + 1) & (NCHUNK - 1);
        stage_a(sbase + OFF_A + 0 * TILE_A, xtiles + (size_t)c0 * TILE_A);
        asm volatile("cp.async.commit_group;" ::: "memory");
        stage_a(sbase + OFF_A + 1 * TILE_A, xtiles + (size_t)c1 * TILE_A);
        asm volatile("cp.async.commit_group;" ::: "memory");
        LDG_B(bregs, wa + c0 * KC);
        CVT_B(bregs, sm, OFF_B16 + 0 * TILE_B16);
        LDG_B(bregs, wa + c1 * KC);
        asm volatile("cp.async.wait_group 1;" ::: "memory");
    }
    __syncthreads();

    int a_slot = 0;   // A buffer index of current chunk (mod 3)
    for (int j = 0; j < NCHUNK; ++j) {
        const int c2 = (start + j + 2) & (NCHUNK - 1);
        const int a_next2 = (a_slot + 2 >= 3) ? (a_slot - 1) : (a_slot + 2);
        const bool pf = (j + 2 < NCHUNK);

        // Prefetch A(c_{j+2}) (group j+2).
        if (pf) {
            stage_a(sbase + OFF_A + (uint32_t)(a_next2 * TILE_A),
                    xtiles + (size_t)c2 * TILE_A);
            asm volatile("cp.async.commit_group;" ::: "memory");
        }

        // MMA on A[a_slot], B16[j&1]: 2 K=16 steps
        const uint32_t abuf = sbase + OFF_A + (uint32_t)(a_slot * TILE_A);
        const uint32_t bbuf = sbase + OFF_B16 + (uint32_t)((j & 1) * TILE_B16);
#pragma unroll
        for (int ks = 0; ks < 2; ++ks) {
            uint32_t ah[4][4], bh[2][4];
#pragma unroll
            for (int mt = 0; mt < 4; ++mt)
                ldm_x4(ah[mt], abuf +
                       SWZ64((a_row + mt * 16) * 64 + ks * 32 + a_cb));
#pragma unroll
            for (int bt = 0; bt < 2; ++bt)
                ldm_x4(bh[bt], bbuf +
                       SWZ64((b_row + bt * 16) * 64 + ks * 32 + b_cb));
#pragma unroll
            for (int mt = 0; mt < 4; ++mt)
#pragma unroll
                for (int nt = 0; nt < 4; ++nt)
                    mma_f16(acc[mt][nt], ah[mt], &bh[nt >> 1][(nt & 1) * 2]);
        }

        // Convert B(c_{j+1}) (resident in regs), then load B(c_{j+2}) into
        // regs — a full chunk of latency cover before its convert.
        if (j + 1 < NCHUNK) {
            CVT_B(bregs, sm, OFF_B16 + (uint32_t)(((j + 1) & 1) * TILE_B16));
            if (j + 2 < NCHUNK) {
                LDG_B(bregs, wa + c2 * KC);
            }
        }

        // Ensure A(c_{j+1}) landed (group j+2 may stay in flight).
        if (pf) {
            asm volatile("cp.async.wait_group 1;" ::: "memory");
        } else {
            asm volatile("cp.async.wait_group 0;" ::: "memory");
        }
        __syncthreads();

        a_slot = (a_slot + 1 >= 3) ? 0 : (a_slot + 1);
    }

    // Epilogue: add bias, store. out[b][o][i] = b*65536 + o*64 + i
    const float* bp = bias + (size_t)(otile * 128) * IDIM + i_idx;
    float bv[4][2];
#pragma unroll
    for (int nt = 0; nt < 4; ++nt) {
        int n_l = warp_n * 32 + nt * 8 + 2 * (lid & 3);
        bv[nt][0] = bp[(size_t)n_l * IDIM];
        bv[nt][1] = bp[(size_t)(n_l + 1) * IDIM];
    }
#pragma unroll
    for (int mt = 0; mt < 4; ++mt) {
        int m0 = warp_m * 64 + mt * 16 + (lid >> 2);
#pragma unroll
        for (int nt = 0; nt < 4; ++nt) {
            int n_l = warp_n * 32 + nt * 8 + 2 * (lid & 3);
            float* o0 = out + (size_t)m0 * (ODIM * IDIM) +
                        (size_t)(otile * 128 + n_l) * IDIM + i_idx;
            o0[0] = acc[mt][nt][0] + bv[nt][0];
            o0[IDIM] = acc[mt][nt][1] + bv[nt][1];
            float* o8 = o0 + (size_t)8 * (ODIM * IDIM);
            o8[0] = acc[mt][nt][2] + bv[nt][0];
            o8[IDIM] = acc[mt][nt][3] + bv[nt][1];
        }
    }
}

extern "C" void kernel_launch(void* const* d_in, const int* in_sizes, int n_in,
                              void* d_out, int out_size) {
    (void)in_sizes; (void)n_in; (void)out_size;
    const float* x = (const float*)d_in[0];
    const float* w = (const float*)d_in[1];
    const float* bias = (const float*)d_in[2];
    float* out = (float*)d_out;

    cvt_x_kernel<<<dim3(IDIM, 8), THREADS>>>(x);

    cudaFuncSetAttribute(fl_kernel, cudaFuncAttributeMaxDynamicSharedMemorySize,
                         SMEM_DYN);
    fl_kernel<<<dim3(ODIM / 128, IDIM), THREADS, SMEM_DYN>>>(w, bias, out);
}

// round 15
// speedup vs baseline: 1.2822x; 1.1831x over previous
#include <cuda_runtime.h>
#include <cuda_fp16.h>
#include <cstdint>

#define KDIM 1024
#define IDIM 64
#define ODIM 1024
#define THREADS 256
#define KC 32                   // k per chunk
#define NCHUNK (KDIM / KC)      // 32 per i; 64 per CTA (i-pair)
#define NCH2 (2 * NCHUNK)

// 64B-row tiles, SW64 XOR swizzle (conflict-free for ldmatrix phases)
#define SWZ64(o) ((uint32_t)(o) ^ ((((uint32_t)(o)) >> 3) & 0x30))
#define TILE_A 8192             // A fp16 tile: 128 x 32 fp16
#define TILE_B16 8192           // B fp16 tile: 128 x 32 fp16

#define OFF_A 0                      // 3 buffers: +0, +8192, +16384
#define OFF_B16 (3 * TILE_A)         // 24576: 2 buffers
#define SMEM_DYN (OFF_B16 + 2 * TILE_B16)   // 40960

// Pre-converted x: tile (i, ch) = 8 KB at ((i*32+ch)*8192); swizzled
// [b(128) x 32 fp16] rows of 64B.
__device__ unsigned char g_xh[64 * 32 * 8192];
// Per-CTA scratch for the i0 result: 256 CTAs x 16 float4-slots x 256 threads.
__device__ float4 g_scr[256 * 16 * 256];

static __device__ __forceinline__ uint32_t smem_u32(const void* p) {
    uint32_t a;
    asm("{ .reg .u64 t; cvta.to.shared.u64 t, %1; cvt.u32.u64 %0, t; }"
        : "=r"(a) : "l"(p));
    return a;
}

static __device__ __forceinline__ void ldm_x4(uint32_t* r, uint32_t addr) {
    asm volatile(
        "ldmatrix.sync.aligned.m8n8.x4.shared.b16 {%0,%1,%2,%3}, [%4];"
        : "=r"(r[0]), "=r"(r[1]), "=r"(r[2]), "=r"(r[3]) : "r"(addr));
}

static __device__ __forceinline__ void mma_f16(float* d, const uint32_t* a,
                                               const uint32_t* b) {
    asm volatile(
        "mma.sync.aligned.m16n8k16.row.col.f32.f16.f16.f32 "
        "{%0,%1,%2,%3}, {%4,%5,%6,%7}, {%8,%9}, {%0,%1,%2,%3};"
        : "+f"(d[0]), "+f"(d[1]), "+f"(d[2]), "+f"(d[3])
        : "r"(a[0]), "r"(a[1]), "r"(a[2]), "r"(a[3]), "r"(b[0]), "r"(b[1]));
}

static __device__ __forceinline__ void cp16(uint32_t saddr, const void* gaddr) {
    asm volatile("cp.async.cg.shared.global [%0], [%1], 16;"
                 :: "r"(saddr), "l"(gaddr));
}

// Pack float4 -> 2 fp16x2 with single-instruction converts.
static __device__ __forceinline__ uint2 pack_hi4(const float4 v) {
    uint2 r;
    asm("cvt.rn.f16x2.f32 %0, %1, %2;" : "=r"(r.x) : "f"(v.y), "f"(v.x));
    asm("cvt.rn.f16x2.f32 %0, %1, %2;" : "=r"(r.y) : "f"(v.w), "f"(v.z));
    return r;
}

// ───────────── pre-pass: x fp32 -> swizzled fp16 tiles (coalesced) ─────────
__global__ void __launch_bounds__(THREADS)
cvt_x_kernel(const float* __restrict__ x) {
    const int i = blockIdx.x;     // 0..63
    const int bb = blockIdx.y;    // 0..7 (16 batch rows each)
    unsigned char* tiles = g_xh + (size_t)i * NCHUNK * TILE_A;
#pragma unroll
    for (int it = 0; it < 16; ++it) {
        int f = threadIdx.x + it * THREADS;   // 0..4095 float4 over [16b x 256c4]
        int b_loc = f >> 8;
        int c4 = f & 255;
        int b = bb * 16 + b_loc;
        const float4 v = *reinterpret_cast<const float4*>(
            x + (size_t)b * (IDIM * KDIM) + (size_t)i * KDIM + c4 * 4);
        int ch = c4 >> 3;
        uint32_t boff = (uint32_t)(b * 64 + (c4 & 7) * 8);
        *reinterpret_cast<uint2*>(tiles + (size_t)ch * TILE_A + SWZ64(boff)) =
            pack_hi4(v);
    }
}

// ───────────── main GEMM ─────────────

static __device__ __forceinline__ void stage_a(uint32_t dst,
                                               const unsigned char* tile) {
#pragma unroll
    for (int it = 0; it < 2; ++it) {
        int g = threadIdx.x + it * THREADS;
        cp16(dst + (uint32_t)(g * 16), tile + (size_t)g * 16);
    }
}

#define LDG_B(bregs, gb)                                                       \
    do {                                                                       \
        _Pragma("unroll") for (int it_ = 0; it_ < 4; ++it_) {                  \
            int f_ = threadIdx.x + it_ * THREADS;                              \
            int row_ = f_ >> 3, c4_ = f_ & 7;                                  \
            (bregs)[it_] = *reinterpret_cast<const float4*>(                   \
                (gb) + (size_t)row_ * 65536 + c4_ * 4);                        \
        }                                                                      \
    } while (0)

#define CVT_B(bregs, sm, dst_off)                                              \
    do {                                                                       \
        _Pragma("unroll") for (int it_ = 0; it_ < 4; ++it_) {                  \
            int f_ = threadIdx.x + it_ * THREADS;                              \
            int row_ = f_ >> 3, c4_ = f_ & 7;                                  \
            *reinterpret_cast<uint2*>((sm) + (dst_off) +                       \
                                      SWZ64(row_ * 64 + c4_ * 8)) =            \
                pack_hi4((bregs)[it_]);                                        \
        }                                                                      \
    } while (0)

__global__ void __launch_bounds__(THREADS, 2)
fl_kernel(const float* __restrict__ w, const float* __restrict__ bias,
          float* __restrict__ out) {
    extern __shared__ char sm[];
    const uint32_t sbase = smem_u32(sm);
    const int tid = threadIdx.x;
    const int wid = tid >> 5;
    const int lid = tid & 31;
    const int warp_m = wid >> 2;   // 0..1 : 64 M rows each
    const int warp_n = wid & 3;    // 0..3 : 32 N cols each
    const int otile = blockIdx.x;  // 0..7
    const int ipair = blockIdx.y;  // 0..31
    const int i0 = ipair * 2;

    // Tile pointers for the two i's
    const unsigned char* xt0 = g_xh + (size_t)i0 * NCHUNK * TILE_A;
    const unsigned char* xt1 = xt0 + (size_t)NCHUNK * TILE_A;
    const float* wbase = w + ((size_t)otile * 128) * (IDIM * KDIM);
    const float* wa0 = wbase + (size_t)i0 * KDIM;
    const float* wa1 = wa0 + KDIM;

    float4* scr = g_scr + ((size_t)(ipair * 8 + otile)) * 16 * 256;

    float acc[4][4][4];
#pragma unroll
    for (int a = 0; a < 4; ++a)
#pragma unroll
        for (int b = 0; b < 4; ++b)
#pragma unroll
            for (int c = 0; c < 4; ++c) acc[a][b][c] = 0.0f;

    const uint32_t a_row = (uint32_t)(warp_m * 64 + (lid & 15));
    const uint32_t a_cb = (uint32_t)((lid >> 4) * 16);
    const uint32_t b_row = (uint32_t)(warp_n * 32 + ((lid >> 4) << 3) + (lid & 7));
    const uint32_t b_cb = (uint32_t)(((lid >> 3) & 1) * 16);

    // chunk index c in [0, 64): i-part = c>>5, k-chunk = c&31
#define XTILE(c) (((c) >> 5) ? xt1 : xt0) + (size_t)((c) & 31) * TILE_A
#define WPTR(c)  ((((c) >> 5) ? wa1 : wa0) + ((c) & 31) * KC)

    // Prologue: chunks 0,1
    float4 bregs[4];
    stage_a(sbase + OFF_A + 0 * TILE_A, XTILE(0));
    asm volatile("cp.async.commit_group;" ::: "memory");
    stage_a(sbase + OFF_A + 1 * TILE_A, XTILE(1));
    asm volatile("cp.async.commit_group;" ::: "memory");
    LDG_B(bregs, WPTR(0));
    CVT_B(bregs, sm, OFF_B16 + 0 * TILE_B16);
    LDG_B(bregs, WPTR(1));
    asm volatile("cp.async.wait_group 1;" ::: "memory");
    __syncthreads();

    int a_slot = 0;
    for (int c = 0; c < NCH2; ++c) {
        const int a_next2 = (a_slot + 2 >= 3) ? (a_slot - 1) : (a_slot + 2);
        const bool pf = (c + 2 < NCH2);

        if (pf) {
            stage_a(sbase + OFF_A + (uint32_t)(a_next2 * TILE_A), XTILE(c + 2));
            asm volatile("cp.async.commit_group;" ::: "memory");
        }

        const uint32_t abuf = sbase + OFF_A + (uint32_t)(a_slot * TILE_A);
        const uint32_t bbuf = sbase + OFF_B16 + (uint32_t)((c & 1) * TILE_B16);
#pragma unroll
        for (int ks = 0; ks < 2; ++ks) {
            uint32_t ah[4][4], bh[2][4];
#pragma unroll
            for (int mt = 0; mt < 4; ++mt)
                ldm_x4(ah[mt], abuf +
                       SWZ64((a_row + mt * 16) * 64 + ks * 32 + a_cb));
#pragma unroll
            for (int bt = 0; bt < 2; ++bt)
                ldm_x4(bh[bt], bbuf +
                       SWZ64((b_row + bt * 16) * 64 + ks * 32 + b_cb));
#pragma unroll
            for (int mt = 0; mt < 4; ++mt)
#pragma unroll
                for (int nt = 0; nt < 4; ++nt)
                    mma_f16(acc[mt][nt], ah[mt], &bh[nt >> 1][(nt & 1) * 2]);
        }

        // End of i0: dump acc(+bias_i0) coalesced to L2 scratch, reset acc.
        if (c == NCHUNK - 1) {
            const float* bp0 = bias + (size_t)(otile * 128) * IDIM + i0;
#pragma unroll
            for (int mt = 0; mt < 4; ++mt)
#pragma unroll
                for (int nt = 0; nt < 4; ++nt) {
                    int n_l = warp_n * 32 + nt * 8 + 2 * (lid & 3);
                    float b0 = bp0[(size_t)n_l * IDIM];
                    float b1 = bp0[(size_t)(n_l + 1) * IDIM];
                    scr[(mt * 4 + nt) * 256 + tid] =
                        make_float4(acc[mt][nt][0] + b0, acc[mt][nt][1] + b1,
                                    acc[mt][nt][2] + b0, acc[mt][nt][3] + b1);
                    acc[mt][nt][0] = 0.0f; acc[mt][nt][1] = 0.0f;
                    acc[mt][nt][2] = 0.0f; acc[mt][nt][3] = 0.0f;
                }
        }

        if (c + 1 < NCH2) {
            CVT_B(bregs, sm, OFF_B16 + (uint32_t)(((c + 1) & 1) * TILE_B16));
            if (c + 2 < NCH2) {
                LDG_B(bregs, WPTR(c + 2));
            }
        }

        if (pf) {
            asm volatile("cp.async.wait_group 1;" ::: "memory");
        } else {
            asm volatile("cp.async.wait_group 0;" ::: "memory");
        }
        __syncthreads();

        a_slot = (a_slot + 1 >= 3) ? 0 : (a_slot + 1);
    }

    // Epilogue: merge i0 (scratch) + i1 (acc+bias), store 8B pairs (i0,i1).
    const float* bp1 = bias + (size_t)(otile * 128) * IDIM + i0 + 1;
#pragma unroll
    for (int mt = 0; mt < 4; ++mt) {
        int m0 = warp_m * 64 + mt * 16 + (lid >> 2);
#pragma unroll
        for (int nt = 0; nt < 4; ++nt) {
            int n_l = warp_n * 32 + nt * 8 + 2 * (lid & 3);
            float b0 = bp1[(size_t)n_l * IDIM];
            float b1 = bp1[(size_t)(n_l + 1) * IDIM];
            const float4 p = scr[(mt * 4 + nt) * 256 + tid];
            float* o0 = out + (size_t)m0 * (ODIM * IDIM) +
                        (size_t)(otile * 128 + n_l) * IDIM + i0;
            *reinterpret_cast<float2*>(o0) =
                make_float2(p.x, acc[mt][nt][0] + b0);
            *reinterpret_cast<float2*>(o0 + IDIM) =
                make_float2(p.y, acc[mt][nt][1] + b1);
            float* o8 = o0 + (size_t)8 * (ODIM * IDIM);
            *reinterpret_cast<float2*>(o8) =
                make_float2(p.z, acc[mt][nt][2] + b0);
            *reinterpret_cast<float2*>(o8 + IDIM) =
                make_float2(p.w, acc[mt][nt][3] + b1);
        }
    }
}

extern "C" void kernel_launch(void* const* d_in, const int* in_sizes, int n_in,
                              void* d_out, int out_size) {
    (void)in_sizes; (void)n_in; (void)out_size;
    const float* x = (const float*)d_in[0];
    const float* w = (const float*)d_in[1];
    const float* bias = (const float*)d_in[2];
    float* out = (float*)d_out;

    cvt_x_kernel<<<dim3(IDIM, 8), THREADS>>>(x);

    cudaFuncSetAttribute(fl_kernel, cudaFuncAttributeMaxDynamicSharedMemorySize,
                         SMEM_DYN);
    fl_kernel<<<dim3(ODIM / 128, IDIM / 2), THREADS, SMEM_DYN>>>(w, bias, out);
}